// round 15
// baseline (speedup 1.0000x reference)
#include <cuda_runtime.h>
#include <cuda_bf16.h>
#include <cuda_fp16.h>
#include <cstdint>

#define B_   2
#define S_   2048
#define H_   1024
#define NH_  16
#define D_   64

#define LOG2E 1.44269504f
#define SCL   (0.125f * LOG2E)   // 1/sqrt(64) * log2(e)

// fp16 operand / result arrays (word = packed half2)
__device__ __align__(16) uint32_t g_Xw[4096 * 512];              // X row-major k-pairs
__device__ __align__(16) uint32_t g_Ww[3 * 1024 * 512];          // W^T: [n][kpair]
__device__ __align__(16) uint32_t g_QKVw[3][B_ * NH_ * S_ * 32]; // Q,K,V head-major d-pairs

__device__ __forceinline__ uint32_t packh2(float lo, float hi) {
    uint32_t r;
    asm("cvt.rn.f16x2.f32 %0, %1, %2;" : "=r"(r) : "f"(hi), "f"(lo));
    return r;
}

__device__ __forceinline__ uint32_t ex2h2(uint32_t a) {
    uint32_t d;
    asm("ex2.approx.f16x2 %0, %1;" : "=r"(d) : "r"(a));
    return d;
}

__device__ __forceinline__ void mma_f16(float c[4], const uint32_t a[4],
                                        uint32_t b0, uint32_t b1) {
    asm volatile(
        "mma.sync.aligned.m16n8k16.row.col.f32.f16.f16.f32 "
        "{%0,%1,%2,%3}, {%4,%5,%6,%7}, {%8,%9}, {%0,%1,%2,%3};\n"
        : "+f"(c[0]), "+f"(c[1]), "+f"(c[2]), "+f"(c[3])
        : "r"(a[0]), "r"(a[1]), "r"(a[2]), "r"(a[3]), "r"(b0), "r"(b1));
}

__device__ __forceinline__ void ldsm4(uint32_t r[4], uint32_t addr) {
    asm volatile("ldmatrix.sync.aligned.m8n8.x4.shared.b16 {%0,%1,%2,%3}, [%4];\n"
        : "=r"(r[0]), "=r"(r[1]), "=r"(r[2]), "=r"(r[3]) : "r"(addr));
}
__device__ __forceinline__ void ldsm4t(uint32_t r[4], uint32_t addr) {
    asm volatile("ldmatrix.sync.aligned.m8n8.x4.trans.shared.b16 {%0,%1,%2,%3}, [%4];\n"
        : "=r"(r[0]), "=r"(r[1]), "=r"(r[2]), "=r"(r[3]) : "r"(addr));
}

__device__ __forceinline__ void cpa16(uint32_t dst, const void* src) {
    asm volatile("cp.async.cg.shared.global [%0], [%1], 16;\n" :: "r"(dst), "l"(src));
}
#define CP_COMMIT() asm volatile("cp.async.commit_group;\n" ::: "memory")
#define CP_WAIT0()  asm volatile("cp.async.wait_group 0;\n" ::: "memory")
#define CP_WAIT1()  asm volatile("cp.async.wait_group 1;\n" ::: "memory")

// ---------------------------------------------------------------------------
// Converters (one-time): fp32 -> fp16 packed layouts
// ---------------------------------------------------------------------------
__global__ __launch_bounds__(256) void cvtX(const float* __restrict__ X) {
    int idx = blockIdx.x * 256 + threadIdx.x;
    float4 v = *reinterpret_cast<const float4*>(&X[(size_t)idx * 4]);
    uint2 u = {packh2(v.x, v.y), packh2(v.z, v.w)};
    *reinterpret_cast<uint2*>(&g_Xw[(size_t)idx * 2]) = u;
}

__global__ __launch_bounds__(256) void cvtW(
    const float* __restrict__ Wq, const float* __restrict__ Wk,
    const float* __restrict__ Wv)
{
    const float* W = (blockIdx.z == 0) ? Wq : (blockIdx.z == 1) ? Wk : Wv;
    int id = blockIdx.x * 256 + threadIdx.x;
    int pg = id >> 10;
    int n  = id & 1023;
    float w[8];
#pragma unroll
    for (int j = 0; j < 8; j++) w[j] = W[(size_t)(pg * 8 + j) * H_ + n];
    uint4 u = {packh2(w[0], w[1]), packh2(w[2], w[3]),
               packh2(w[4], w[5]), packh2(w[6], w[7])};
    *reinterpret_cast<uint4*>(&g_Ww[(size_t)blockIdx.z * 524288 + (size_t)n * 512 + pg * 4]) = u;
}

// ---------------------------------------------------------------------------
// Fused QKV GEMM. 3-stage cp.async pipeline, single barrier per k-chunk.
// __launch_bounds__(256, 2): cap regs at 128 so 2 blocks co-reside per SM
// (16 warps/SM; was 1 block = 8 warps at 168 regs).
// ---------------------------------------------------------------------------
__global__ __launch_bounds__(256, 2) void qkv_gemm(
    const float* __restrict__ bq, const float* __restrict__ bk,
    const float* __restrict__ bv)
{
    extern __shared__ __align__(128) uint32_t smq[];

    const int z = blockIdx.z;
    const float* bias = (z == 0) ? bq : (z == 1) ? bk : bv;

    const int tid   = threadIdx.x;
    const int wid   = tid >> 5;
    const int lane  = tid & 31;
    const int g     = lane >> 2;
    const int tg    = lane & 3;
    const int warpM = wid >> 1;
    const int warpN = wid & 1;
    const int row0  = blockIdx.y * 128;
    const int col0  = blockIdx.x * 128;

    const uint32_t AO = (uint32_t)__cvta_generic_to_shared(smq);   // 3 x 10240 B
    const uint32_t BO = AO + 30720;                                 // 3 x 10240 B
    const uint32_t* Wz = g_Ww + (size_t)z * 524288;

    const int m8 = lane >> 3;
    const int r8 = lane & 7;
    const uint32_t abase = AO + (uint32_t)(((warpM * 32 + (m8 & 1) * 8 + r8) * 20 + (m8 >> 1) * 4) * 4);
    const uint32_t bbase = BO + (uint32_t)(((warpN * 64 + (m8 >> 1) * 8 + r8) * 20) * 4 + (m8 & 1) * 16);

    float c[2][8][4];
#pragma unroll
    for (int mt = 0; mt < 2; mt++)
#pragma unroll
        for (int nt = 0; nt < 8; nt++)
#pragma unroll
            for (int j = 0; j < 4; j++) c[mt][nt][j] = 0.f;

    auto stage = [&](int kc, int buf) {
#pragma unroll
        for (int p = 0; p < 2; p++) {
            int cid = p * 256 + tid;
            int r = cid >> 2, ch = cid & 3;
            cpa16(AO + (uint32_t)(buf * 10240 + r * 80 + ch * 16),
                  g_Xw + (size_t)(row0 + r) * 512 + kc * 16 + ch * 4);
            cpa16(BO + (uint32_t)(buf * 10240 + r * 80 + ch * 16),
                  Wz + (size_t)(col0 + r) * 512 + kc * 16 + ch * 4);
        }
    };

    stage(0, 0); CP_COMMIT();
    stage(1, 1); CP_COMMIT();

    int buf = 0;
    for (int kc = 0; kc < 32; kc++) {
        CP_WAIT1();                         // chunk kc ready
        __syncthreads();                    // visibility + buffer (kc-1)%3 free
        if (kc + 2 < 32) stage(kc + 2, (buf + 2) % 3);
        CP_COMMIT();
        const uint32_t ofs = (uint32_t)(buf * 10240);

#pragma unroll
        for (int kk = 0; kk < 2; kk++) {
            uint32_t a[2][4];
            ldsm4(a[0], abase + ofs + kk * 32);
            ldsm4(a[1], abase + ofs + 16 * 80 + kk * 32);
#pragma unroll
            for (int ntp = 0; ntp < 4; ntp++) {
                uint32_t bb[4];
                ldsm4(bb, bbase + ofs + ntp * 16 * 80 + kk * 32);
                mma_f16(c[0][2 * ntp],     a[0], bb[0], bb[1]);
                mma_f16(c[1][2 * ntp],     a[1], bb[0], bb[1]);
                mma_f16(c[0][2 * ntp + 1], a[0], bb[2], bb[3]);
                mma_f16(c[1][2 * ntp + 1], a[1], bb[2], bb[3]);
            }
        }
        buf = (buf + 1) % 3;
    }

    const int head = ((col0 + warpN * 64) >> 6);
#pragma unroll
    for (int mt = 0; mt < 2; mt++) {
#pragma unroll
        for (int nt = 0; nt < 8; nt++) {
            int dd   = nt * 8 + 2 * tg;
            int coln = col0 + warpN * 64 + dd;
            float b0 = bias[coln], b1 = bias[coln + 1];
            int r0 = row0 + warpM * 32 + mt * 16 + g;
            int r1 = r0 + 8;
            int bb0 = r0 >> 11, s0 = r0 & 2047;
            int bb1 = r1 >> 11, s1 = r1 & 2047;
            g_QKVw[z][((size_t)(bb0 * NH_ + head) * S_ + s0) * 32 + (dd >> 1)] =
                packh2(c[mt][nt][0] + b0, c[mt][nt][1] + b1);
            g_QKVw[z][((size_t)(bb1 * NH_ + head) * S_ + s1) * 32 + (dd >> 1)] =
                packh2(c[mt][nt][2] + b0, c[mt][nt][3] + b1);
        }
    }
}

// ---------------------------------------------------------------------------
// Flash attention (R14): 4 warps x 32 q-rows, double-buffered K/V, single
// barrier per tile, smem mask, f16x2 exp, l = P@ones.
// ---------------------------------------------------------------------------
__global__ __launch_bounds__(128, 3) void attention(
    const float* __restrict__ mask, float* __restrict__ out)
{
    extern __shared__ __align__(128) uint32_t smu[];
    float* msk = (float*)(smu + 13824);       // [2048] pre-scaled by log2(e)

    const int tid  = threadIdx.x;
    const int w    = tid >> 5;
    const int lane = tid & 31;
    const int g    = lane >> 2;
    const int tg   = lane & 3;
    const int rb   = w * 32;
    const int qt   = blockIdx.x;
    const int head = blockIdx.y;
    const int b    = blockIdx.z;
    const int bh   = b * NH_ + head;

    const uint32_t smb = (uint32_t)__cvta_generic_to_shared(smu);
    const uint32_t QO = smb;                 // [128][36] words
    const uint32_t KO = smb + 4608 * 4;      // 2 x 9216 B
    const uint32_t VO = smb + 9216 * 4;      // 2 x 9216 B

    const uint32_t* Qsrc = g_QKVw[0] + ((size_t)bh * S_ + qt * 128) * 32;
    const uint32_t* Ksrc = g_QKVw[1] + (size_t)bh * S_ * 32;
    const uint32_t* Vsrc = g_QKVw[2] + (size_t)bh * S_ * 32;

    const int m8 = lane >> 3;
    const int r8 = lane & 7;
    const uint32_t qbase = QO + (uint32_t)(((rb + (m8 & 1) * 8 + r8) * 36 + (m8 >> 1) * 4) * 4);
    const uint32_t kbase = (uint32_t)(((m8 >> 1) * 8 + r8) * 144 + (m8 & 1) * 16);
    const uint32_t vbase = (uint32_t)(((m8 & 1) * 8 + r8) * 144 + (m8 >> 1) * 16);

    auto stageKV = [&](int t, int buf) {
#pragma unroll
        for (int p = 0; p < 4; p++) {
            int cid = p * 128 + tid;
            int r = cid >> 3, ch = cid & 7;
            cpa16(KO + (uint32_t)(buf * 9216 + r * 144 + ch * 16),
                  Ksrc + (size_t)(t * 64 + r) * 32 + ch * 4);
            cpa16(VO + (uint32_t)(buf * 9216 + r * 144 + ch * 16),
                  Vsrc + (size_t)(t * 64 + r) * 32 + ch * 4);
        }
    };

#pragma unroll
    for (int p = 0; p < 8; p++) {
        int cid = p * 128 + tid;
        int r = cid >> 3, ch = cid & 7;
        cpa16(QO + (uint32_t)(r * 144 + ch * 16), Qsrc + (size_t)r * 32 + ch * 4);
    }
    stageKV(0, 0);
    CP_COMMIT();
    for (int i = tid; i < S_; i += 128) msk[i] = mask[(size_t)b * S_ + i] * LOG2E;

    float o[2][8][4];
#pragma unroll
    for (int mt = 0; mt < 2; mt++)
#pragma unroll
        for (int nt = 0; nt < 8; nt++)
#pragma unroll
            for (int j = 0; j < 4; j++) o[mt][nt][j] = 0.f;
    float lsum[2][4];
#pragma unroll
    for (int mt = 0; mt < 2; mt++)
#pragma unroll
        for (int j = 0; j < 4; j++) lsum[mt][j] = 0.f;

    const uint32_t ONES = 0x3C003C00u;

    for (int t = 0; t < 32; t++) {
        CP_WAIT0();                      // tile t arrived
        __syncthreads();                 // visibility + buffer (t+1)&1 free
        if (t + 1 < 32) stageKV(t + 1, (t + 1) & 1);
        CP_COMMIT();

        const uint32_t Kbuf = KO + (t & 1) * 9216 + kbase;
        const uint32_t Vbuf = VO + (t & 1) * 9216 + vbase;
        const float2* mrow = (const float2*)(msk + t * 64) + tg;

        float s[2][8][4];
#pragma unroll
        for (int mt = 0; mt < 2; mt++)
#pragma unroll
            for (int nt = 0; nt < 8; nt++)
#pragma unroll
                for (int j = 0; j < 4; j++) s[mt][nt][j] = 0.f;

#pragma unroll
        for (int kk = 0; kk < 4; kk++) {
            uint32_t aq[2][4];
            ldsm4(aq[0], qbase + kk * 32);
            ldsm4(aq[1], qbase + 2304 + kk * 32);
#pragma unroll
            for (int ntp = 0; ntp < 4; ntp++) {
                uint32_t kb[4];
                ldsm4(kb, Kbuf + ntp * 2304 + kk * 32);
                mma_f16(s[0][2 * ntp],     aq[0], kb[0], kb[1]);
                mma_f16(s[1][2 * ntp],     aq[1], kb[0], kb[1]);
                mma_f16(s[0][2 * ntp + 1], aq[0], kb[2], kb[3]);
                mma_f16(s[1][2 * ntp + 1], aq[1], kb[2], kb[3]);
            }
        }

        uint32_t ps[2][8][2];
#pragma unroll
        for (int mt = 0; mt < 2; mt++) {
#pragma unroll
            for (int nt = 0; nt < 8; nt++) {
                float2 mv = mrow[nt * 4];
                float a0 = fminf(s[mt][nt][0] * SCL + mv.x, 15.f);
                float a1 = fminf(s[mt][nt][1] * SCL + mv.y, 15.f);
                float a2 = fminf(s[mt][nt][2] * SCL + mv.x, 15.f);
                float a3 = fminf(s[mt][nt][3] * SCL + mv.y, 15.f);
                ps[mt][nt][0] = ex2h2(packh2(a0, a1));
                ps[mt][nt][1] = ex2h2(packh2(a2, a3));
            }
        }

#pragma unroll
        for (int kk = 0; kk < 4; kk++) {
            uint32_t ap[2][4];
#pragma unroll
            for (int mt = 0; mt < 2; mt++) {
                ap[mt][0] = ps[mt][2 * kk][0];
                ap[mt][1] = ps[mt][2 * kk][1];
                ap[mt][2] = ps[mt][2 * kk + 1][0];
                ap[mt][3] = ps[mt][2 * kk + 1][1];
            }
            mma_f16(lsum[0], ap[0], ONES, ONES);
            mma_f16(lsum[1], ap[1], ONES, ONES);
#pragma unroll
            for (int ntp = 0; ntp < 4; ntp++) {
                uint32_t vb[4];
                ldsm4t(vb, Vbuf + kk * 2304 + ntp * 32);
                mma_f16(o[0][2 * ntp],     ap[0], vb[0], vb[1]);
                mma_f16(o[1][2 * ntp],     ap[1], vb[0], vb[1]);
                mma_f16(o[0][2 * ntp + 1], ap[0], vb[2], vb[3]);
                mma_f16(o[1][2 * ntp + 1], ap[1], vb[2], vb[3]);
            }
        }
    }

#pragma unroll
    for (int mt = 0; mt < 2; mt++) {
        float i0 = 1.0f / lsum[mt][0], i1 = 1.0f / lsum[mt][2];
        int r0 = qt * 128 + rb + mt * 16 + g;
        int r1 = r0 + 8;
#pragma unroll
        for (int nt = 0; nt < 8; nt++) {
            int dd = head * 64 + nt * 8 + 2 * tg;
            float2 v0 = {o[mt][nt][0] * i0, o[mt][nt][1] * i0};
            float2 v1 = {o[mt][nt][2] * i1, o[mt][nt][3] * i1};
            *reinterpret_cast<float2*>(&out[((size_t)b * S_ + r0) * H_ + dd]) = v0;
            *reinterpret_cast<float2*>(&out[((size_t)b * S_ + r1) * H_ + dd]) = v1;
        }
    }
}

// ---------------------------------------------------------------------------
extern "C" void kernel_launch(void* const* d_in, const int* in_sizes, int n_in,
                              void* d_out, int out_size)
{
    const float* hs   = (const float*)d_in[0];
    const float* mask = (const float*)d_in[1];
    const float* Wq   = (const float*)d_in[2];
    const float* bq   = (const float*)d_in[3];
    const float* Wk   = (const float*)d_in[4];
    const float* bk   = (const float*)d_in[5];
    const float* Wv   = (const float*)d_in[6];
    const float* bv   = (const float*)d_in[7];
    float* out = (float*)d_out;

    cudaFuncSetAttribute(qkv_gemm, cudaFuncAttributeMaxDynamicSharedMemorySize, 61440);
    cudaFuncSetAttribute(attention, cudaFuncAttributeMaxDynamicSharedMemorySize, 63488);

    cvtX<<<4096, 256>>>(hs);
    dim3 gW(512, 1, 3);
    cvtW<<<gW, 256>>>(Wq, Wk, Wv);

    dim3 ggemm(H_ / 128, (B_ * S_) / 128, 3);   // fused Q/K/V
    qkv_gemm<<<ggemm, 256, 61440>>>(bq, bk, bv);

    dim3 gattn(S_ / 128, NH_, B_);              // (16, 16, 2)
    attention<<<gattn, 128, 63488>>>(mask, out);
}

// round 16
// speedup vs baseline: 1.4879x; 1.4879x over previous
#include <cuda_runtime.h>
#include <cuda_bf16.h>
#include <cuda_fp16.h>
#include <cstdint>

#define B_   2
#define S_   2048
#define H_   1024
#define NH_  16
#define D_   64

#define LOG2E 1.44269504f
#define SCL   (0.125f * LOG2E)   // 1/sqrt(64) * log2(e)

// fp16 operand / result arrays (word = packed half2)
__device__ __align__(16) uint32_t g_Xw[4096 * 512];              // X row-major k-pairs
__device__ __align__(16) uint32_t g_Ww[3 * 1024 * 512];          // W^T: [n][kpair]
__device__ __align__(16) uint32_t g_QKVw[3][B_ * NH_ * S_ * 32]; // Q,K,V head-major d-pairs

// split-K attention scratch: partial O (unnormalized) and partial l
__device__ __align__(16) float g_Op[2][B_ * NH_ * S_ * D_];      // [split][bh][row][d]
__device__ __align__(16) float g_L[2][B_ * NH_ * S_];            // [split][bh][row]

__device__ __forceinline__ uint32_t packh2(float lo, float hi) {
    uint32_t r;
    asm("cvt.rn.f16x2.f32 %0, %1, %2;" : "=r"(r) : "f"(hi), "f"(lo));
    return r;
}

__device__ __forceinline__ uint32_t ex2h2(uint32_t a) {
    uint32_t d;
    asm("ex2.approx.f16x2 %0, %1;" : "=r"(d) : "r"(a));
    return d;
}

__device__ __forceinline__ void mma_f16(float c[4], const uint32_t a[4],
                                        uint32_t b0, uint32_t b1) {
    asm volatile(
        "mma.sync.aligned.m16n8k16.row.col.f32.f16.f16.f32 "
        "{%0,%1,%2,%3}, {%4,%5,%6,%7}, {%8,%9}, {%0,%1,%2,%3};\n"
        : "+f"(c[0]), "+f"(c[1]), "+f"(c[2]), "+f"(c[3])
        : "r"(a[0]), "r"(a[1]), "r"(a[2]), "r"(a[3]), "r"(b0), "r"(b1));
}

__device__ __forceinline__ void ldsm4(uint32_t r[4], uint32_t addr) {
    asm volatile("ldmatrix.sync.aligned.m8n8.x4.shared.b16 {%0,%1,%2,%3}, [%4];\n"
        : "=r"(r[0]), "=r"(r[1]), "=r"(r[2]), "=r"(r[3]) : "r"(addr));
}
__device__ __forceinline__ void ldsm4t(uint32_t r[4], uint32_t addr) {
    asm volatile("ldmatrix.sync.aligned.m8n8.x4.trans.shared.b16 {%0,%1,%2,%3}, [%4];\n"
        : "=r"(r[0]), "=r"(r[1]), "=r"(r[2]), "=r"(r[3]) : "r"(addr));
}

__device__ __forceinline__ void cpa16(uint32_t dst, const void* src) {
    asm volatile("cp.async.cg.shared.global [%0], [%1], 16;\n" :: "r"(dst), "l"(src));
}
#define CP_COMMIT() asm volatile("cp.async.commit_group;\n" ::: "memory")
#define CP_WAIT0()  asm volatile("cp.async.wait_group 0;\n" ::: "memory")
#define CP_WAIT1()  asm volatile("cp.async.wait_group 1;\n" ::: "memory")

// ---------------------------------------------------------------------------
// Converters (one-time): fp32 -> fp16 packed layouts
// ---------------------------------------------------------------------------
__global__ __launch_bounds__(256) void cvtX(const float* __restrict__ X) {
    int idx = blockIdx.x * 256 + threadIdx.x;
    float4 v = *reinterpret_cast<const float4*>(&X[(size_t)idx * 4]);
    uint2 u = {packh2(v.x, v.y), packh2(v.z, v.w)};
    *reinterpret_cast<uint2*>(&g_Xw[(size_t)idx * 2]) = u;
}

__global__ __launch_bounds__(256) void cvtW(
    const float* __restrict__ Wq, const float* __restrict__ Wk,
    const float* __restrict__ Wv)
{
    const float* W = (blockIdx.z == 0) ? Wq : (blockIdx.z == 1) ? Wk : Wv;
    int id = blockIdx.x * 256 + threadIdx.x;
    int pg = id >> 10;
    int n  = id & 1023;
    float w[8];
#pragma unroll
    for (int j = 0; j < 8; j++) w[j] = W[(size_t)(pg * 8 + j) * H_ + n];
    uint4 u = {packh2(w[0], w[1]), packh2(w[2], w[3]),
               packh2(w[4], w[5]), packh2(w[6], w[7])};
    *reinterpret_cast<uint4*>(&g_Ww[(size_t)blockIdx.z * 524288 + (size_t)n * 512 + pg * 4]) = u;
}

// ---------------------------------------------------------------------------
// Fused QKV GEMM (R14: 3-stage cp.async, single barrier/chunk, no reg cap).
// ---------------------------------------------------------------------------
__global__ __launch_bounds__(256) void qkv_gemm(
    const float* __restrict__ bq, const float* __restrict__ bk,
    const float* __restrict__ bv)
{
    extern __shared__ __align__(128) uint32_t smq[];

    const int z = blockIdx.z;
    const float* bias = (z == 0) ? bq : (z == 1) ? bk : bv;

    const int tid   = threadIdx.x;
    const int wid   = tid >> 5;
    const int lane  = tid & 31;
    const int g     = lane >> 2;
    const int tg    = lane & 3;
    const int warpM = wid >> 1;
    const int warpN = wid & 1;
    const int row0  = blockIdx.y * 128;
    const int col0  = blockIdx.x * 128;

    const uint32_t AO = (uint32_t)__cvta_generic_to_shared(smq);   // 3 x 10240 B
    const uint32_t BO = AO + 30720;                                 // 3 x 10240 B
    const uint32_t* Wz = g_Ww + (size_t)z * 524288;

    const int m8 = lane >> 3;
    const int r8 = lane & 7;
    const uint32_t abase = AO + (uint32_t)(((warpM * 32 + (m8 & 1) * 8 + r8) * 20 + (m8 >> 1) * 4) * 4);
    const uint32_t bbase = BO + (uint32_t)(((warpN * 64 + (m8 >> 1) * 8 + r8) * 20) * 4 + (m8 & 1) * 16);

    float c[2][8][4];
#pragma unroll
    for (int mt = 0; mt < 2; mt++)
#pragma unroll
        for (int nt = 0; nt < 8; nt++)
#pragma unroll
            for (int j = 0; j < 4; j++) c[mt][nt][j] = 0.f;

    auto stage = [&](int kc, int buf) {
#pragma unroll
        for (int p = 0; p < 2; p++) {
            int cid = p * 256 + tid;
            int r = cid >> 2, ch = cid & 3;
            cpa16(AO + (uint32_t)(buf * 10240 + r * 80 + ch * 16),
                  g_Xw + (size_t)(row0 + r) * 512 + kc * 16 + ch * 4);
            cpa16(BO + (uint32_t)(buf * 10240 + r * 80 + ch * 16),
                  Wz + (size_t)(col0 + r) * 512 + kc * 16 + ch * 4);
        }
    };

    stage(0, 0); CP_COMMIT();
    stage(1, 1); CP_COMMIT();

    int buf = 0;
    for (int kc = 0; kc < 32; kc++) {
        CP_WAIT1();
        __syncthreads();
        if (kc + 2 < 32) stage(kc + 2, (buf + 2) % 3);
        CP_COMMIT();
        const uint32_t ofs = (uint32_t)(buf * 10240);

#pragma unroll
        for (int kk = 0; kk < 2; kk++) {
            uint32_t a[2][4];
            ldsm4(a[0], abase + ofs + kk * 32);
            ldsm4(a[1], abase + ofs + 16 * 80 + kk * 32);
#pragma unroll
            for (int ntp = 0; ntp < 4; ntp++) {
                uint32_t bb[4];
                ldsm4(bb, bbase + ofs + ntp * 16 * 80 + kk * 32);
                mma_f16(c[0][2 * ntp],     a[0], bb[0], bb[1]);
                mma_f16(c[1][2 * ntp],     a[1], bb[0], bb[1]);
                mma_f16(c[0][2 * ntp + 1], a[0], bb[2], bb[3]);
                mma_f16(c[1][2 * ntp + 1], a[1], bb[2], bb[3]);
            }
        }
        buf = (buf + 1) % 3;
    }

    const int head = ((col0 + warpN * 64) >> 6);
#pragma unroll
    for (int mt = 0; mt < 2; mt++) {
#pragma unroll
        for (int nt = 0; nt < 8; nt++) {
            int dd   = nt * 8 + 2 * tg;
            int coln = col0 + warpN * 64 + dd;
            float b0 = bias[coln], b1 = bias[coln + 1];
            int r0 = row0 + warpM * 32 + mt * 16 + g;
            int r1 = r0 + 8;
            int bb0 = r0 >> 11, s0 = r0 & 2047;
            int bb1 = r1 >> 11, s1 = r1 & 2047;
            g_QKVw[z][((size_t)(bb0 * NH_ + head) * S_ + s0) * 32 + (dd >> 1)] =
                packh2(c[mt][nt][0] + b0, c[mt][nt][1] + b1);
            g_QKVw[z][((size_t)(bb1 * NH_ + head) * S_ + s1) * 32 + (dd >> 1)] =
                packh2(c[mt][nt][2] + b0, c[mt][nt][3] + b1);
        }
    }
}

// ---------------------------------------------------------------------------
// Flash attention, SPLIT-K over the key dimension (2 splits of 16 KV tiles).
// Fixed-max softmax makes O and l plain sums -> partials are additive.
// Writes unnormalized partial O + partial l; combine kernel finishes.
// blockIdx: x = qt (16), y = head (16), z = b*2 + split (4).
// ---------------------------------------------------------------------------
__global__ __launch_bounds__(128, 3) void attention(
    const float* __restrict__ mask)
{
    extern __shared__ __align__(128) uint32_t smu[];
    float* msk = (float*)(smu + 13824);       // [1024] pre-scaled by log2(e)

    const int tid  = threadIdx.x;
    const int w    = tid >> 5;
    const int lane = tid & 31;
    const int g    = lane >> 2;
    const int tg   = lane & 3;
    const int rb   = w * 32;
    const int qt    = blockIdx.x;
    const int head  = blockIdx.y;
    const int b     = blockIdx.z >> 1;
    const int split = blockIdx.z & 1;
    const int bh    = b * NH_ + head;

    const uint32_t smb = (uint32_t)__cvta_generic_to_shared(smu);
    const uint32_t QO = smb;                 // 18432 B
    const uint32_t KO = smb + 18432;         // 2 x 9216 B
    const uint32_t VO = smb + 36864;         // 2 x 9216 B ; msk @55296 (4 KB)

    const uint32_t* Qsrc = g_QKVw[0] + ((size_t)bh * S_ + qt * 128) * 32;
    const uint32_t* Ksrc = g_QKVw[1] + ((size_t)bh * S_ + split * 1024) * 32;
    const uint32_t* Vsrc = g_QKVw[2] + ((size_t)bh * S_ + split * 1024) * 32;

    const int m8 = lane >> 3;
    const int r8 = lane & 7;
    const uint32_t qbase = QO + (uint32_t)(((rb + (m8 & 1) * 8 + r8) * 36 + (m8 >> 1) * 4) * 4);
    const uint32_t kbase = (uint32_t)(((m8 >> 1) * 8 + r8) * 144 + (m8 & 1) * 16);
    const uint32_t vbase = (uint32_t)(((m8 & 1) * 8 + r8) * 144 + (m8 >> 1) * 16);

    auto stageKV = [&](int t, int buf) {
#pragma unroll
        for (int p = 0; p < 4; p++) {
            int cid = p * 128 + tid;
            int r = cid >> 3, ch = cid & 7;
            cpa16(KO + (uint32_t)(buf * 9216 + r * 144 + ch * 16),
                  Ksrc + (size_t)(t * 64 + r) * 32 + ch * 4);
            cpa16(VO + (uint32_t)(buf * 9216 + r * 144 + ch * 16),
                  Vsrc + (size_t)(t * 64 + r) * 32 + ch * 4);
        }
    };

    // Prologue: Q + tile 0 in group 0; this split's mask half via plain loads
#pragma unroll
    for (int p = 0; p < 8; p++) {
        int cid = p * 128 + tid;
        int r = cid >> 3, ch = cid & 7;
        cpa16(QO + (uint32_t)(r * 144 + ch * 16), Qsrc + (size_t)r * 32 + ch * 4);
    }
    stageKV(0, 0);
    CP_COMMIT();
    for (int i = tid; i < 1024; i += 128)
        msk[i] = mask[(size_t)b * S_ + split * 1024 + i] * LOG2E;

    float o[2][8][4];
#pragma unroll
    for (int mt = 0; mt < 2; mt++)
#pragma unroll
        for (int nt = 0; nt < 8; nt++)
#pragma unroll
            for (int j = 0; j < 4; j++) o[mt][nt][j] = 0.f;
    float lsum[2][4];
#pragma unroll
    for (int mt = 0; mt < 2; mt++)
#pragma unroll
        for (int j = 0; j < 4; j++) lsum[mt][j] = 0.f;

    const uint32_t ONES = 0x3C003C00u;

    for (int t = 0; t < 16; t++) {
        CP_WAIT0();                      // tile t arrived
        __syncthreads();                 // visibility + buffer (t+1)&1 free
        if (t + 1 < 16) stageKV(t + 1, (t + 1) & 1);
        CP_COMMIT();

        const uint32_t Kbuf = KO + (t & 1) * 9216 + kbase;
        const uint32_t Vbuf = VO + (t & 1) * 9216 + vbase;
        const float2* mrow = (const float2*)(msk + t * 64) + tg;

        float s[2][8][4];
#pragma unroll
        for (int mt = 0; mt < 2; mt++)
#pragma unroll
            for (int nt = 0; nt < 8; nt++)
#pragma unroll
                for (int j = 0; j < 4; j++) s[mt][nt][j] = 0.f;

#pragma unroll
        for (int kk = 0; kk < 4; kk++) {
            uint32_t aq[2][4];
            ldsm4(aq[0], qbase + kk * 32);
            ldsm4(aq[1], qbase + 2304 + kk * 32);
#pragma unroll
            for (int ntp = 0; ntp < 4; ntp++) {
                uint32_t kb[4];
                ldsm4(kb, Kbuf + ntp * 2304 + kk * 32);
                mma_f16(s[0][2 * ntp],     aq[0], kb[0], kb[1]);
                mma_f16(s[1][2 * ntp],     aq[1], kb[0], kb[1]);
                mma_f16(s[0][2 * ntp + 1], aq[0], kb[2], kb[3]);
                mma_f16(s[1][2 * ntp + 1], aq[1], kb[2], kb[3]);
            }
        }

        uint32_t ps[2][8][2];
#pragma unroll
        for (int mt = 0; mt < 2; mt++) {
#pragma unroll
            for (int nt = 0; nt < 8; nt++) {
                float2 mv = mrow[nt * 4];
                float a0 = fminf(s[mt][nt][0] * SCL + mv.x, 15.f);
                float a1 = fminf(s[mt][nt][1] * SCL + mv.y, 15.f);
                float a2 = fminf(s[mt][nt][2] * SCL + mv.x, 15.f);
                float a3 = fminf(s[mt][nt][3] * SCL + mv.y, 15.f);
                ps[mt][nt][0] = ex2h2(packh2(a0, a1));
                ps[mt][nt][1] = ex2h2(packh2(a2, a3));
            }
        }

#pragma unroll
        for (int kk = 0; kk < 4; kk++) {
            uint32_t ap[2][4];
#pragma unroll
            for (int mt = 0; mt < 2; mt++) {
                ap[mt][0] = ps[mt][2 * kk][0];
                ap[mt][1] = ps[mt][2 * kk][1];
                ap[mt][2] = ps[mt][2 * kk + 1][0];
                ap[mt][3] = ps[mt][2 * kk + 1][1];
            }
            mma_f16(lsum[0], ap[0], ONES, ONES);
            mma_f16(lsum[1], ap[1], ONES, ONES);
#pragma unroll
            for (int ntp = 0; ntp < 4; ntp++) {
                uint32_t vb[4];
                ldsm4t(vb, Vbuf + kk * 2304 + ntp * 32);
                mma_f16(o[0][2 * ntp],     ap[0], vb[0], vb[1]);
                mma_f16(o[1][2 * ntp],     ap[1], vb[0], vb[1]);
                mma_f16(o[0][2 * ntp + 1], ap[0], vb[2], vb[3]);
                mma_f16(o[1][2 * ntp + 1], ap[1], vb[2], vb[3]);
            }
        }
    }

    // ---- Epilogue: write UNNORMALIZED partial O + partial l
    float* Op = g_Op[split] + (size_t)bh * S_ * D_;
    float* Lp = g_L[split] + (size_t)bh * S_;
#pragma unroll
    for (int mt = 0; mt < 2; mt++) {
        int r0 = qt * 128 + rb + mt * 16 + g;
        int r1 = r0 + 8;
#pragma unroll
        for (int nt = 0; nt < 8; nt++) {
            int dd = nt * 8 + 2 * tg;
            float2 v0 = {o[mt][nt][0], o[mt][nt][1]};
            float2 v1 = {o[mt][nt][2], o[mt][nt][3]};
            *reinterpret_cast<float2*>(&Op[(size_t)r0 * D_ + dd]) = v0;
            *reinterpret_cast<float2*>(&Op[(size_t)r1 * D_ + dd]) = v1;
        }
        if (tg == 0) {
            Lp[r0] = lsum[mt][0];
            Lp[r1] = lsum[mt][2];
        }
    }
}

// ---------------------------------------------------------------------------
// Combine: out = (O0 + O1) / (l0 + l1), scattered to [b, s, head*64 + d].
// ---------------------------------------------------------------------------
__global__ __launch_bounds__(256) void combine(float* __restrict__ out)
{
    size_t idx  = (size_t)blockIdx.x * 256 + threadIdx.x;   // 1M threads x float4
    size_t flat = idx * 4;
    int dd   = (int)(flat & 63);
    int head = (int)((flat >> 6) & 15);
    int row  = (int)((flat >> 10) & 2047);
    int b    = (int)(flat >> 21);
    int bh   = b * NH_ + head;

    size_t po = ((size_t)bh * S_ + row) * D_ + dd;
    float4 a = *reinterpret_cast<const float4*>(&g_Op[0][po]);
    float4 c = *reinterpret_cast<const float4*>(&g_Op[1][po]);
    float  l = g_L[0][(size_t)bh * S_ + row] + g_L[1][(size_t)bh * S_ + row];
    float inv = 1.0f / l;
    float4 r = {(a.x + c.x) * inv, (a.y + c.y) * inv,
                (a.z + c.z) * inv, (a.w + c.w) * inv};
    *reinterpret_cast<float4*>(&out[flat]) = r;
}

// ---------------------------------------------------------------------------
extern "C" void kernel_launch(void* const* d_in, const int* in_sizes, int n_in,
                              void* d_out, int out_size)
{
    const float* hs   = (const float*)d_in[0];
    const float* mask = (const float*)d_in[1];
    const float* Wq   = (const float*)d_in[2];
    const float* bq   = (const float*)d_in[3];
    const float* Wk   = (const float*)d_in[4];
    const float* bk   = (const float*)d_in[5];
    const float* Wv   = (const float*)d_in[6];
    const float* bv   = (const float*)d_in[7];
    float* out = (float*)d_out;

    cudaFuncSetAttribute(qkv_gemm, cudaFuncAttributeMaxDynamicSharedMemorySize, 61440);
    cudaFuncSetAttribute(attention, cudaFuncAttributeMaxDynamicSharedMemorySize, 59392);

    cvtX<<<4096, 256>>>(hs);
    dim3 gW(512, 1, 3);
    cvtW<<<gW, 256>>>(Wq, Wk, Wv);

    dim3 ggemm(H_ / 128, (B_ * S_) / 128, 3);   // fused Q/K/V
    qkv_gemm<<<ggemm, 256, 61440>>>(bq, bk, bv);

    dim3 gattn(S_ / 128, NH_, B_ * 2);          // (16, 16, 4) — 2 KV splits
    attention<<<gattn, 128, 59392>>>(mask);

    combine<<<4096, 256>>>(out);
}

// round 17
// speedup vs baseline: 1.5027x; 1.0099x over previous
#include <cuda_runtime.h>
#include <cuda_bf16.h>
#include <cuda_fp16.h>
#include <cstdint>

#define B_   2
#define S_   2048
#define H_   1024
#define NH_  16
#define D_   64

#define LOG2E 1.44269504f
#define SCL   (0.125f * LOG2E)   // 1/sqrt(64) * log2(e)

// fp16 operand / result arrays (word = packed half2)
__device__ __align__(16) uint32_t g_Xw[4096 * 512];              // X row-major k-pairs
__device__ __align__(16) uint32_t g_Ww[3 * 1024 * 512];          // W^T: [n][kpair]
__device__ __align__(16) uint32_t g_QKVw[3][B_ * NH_ * S_ * 32]; // Q,K,V head-major d-pairs

// split-K attention scratch + completion flags (zero-initialized)
__device__ __align__(16) float g_Op[2][B_ * NH_ * S_ * D_];      // [split][bh][row][d]
__device__ __align__(16) float g_L[2][B_ * NH_ * S_];            // [split][bh][row]
__device__ int g_flag[B_ * NH_ * 16];                            // per (bh, qt)

__device__ __forceinline__ uint32_t packh2(float lo, float hi) {
    uint32_t r;
    asm("cvt.rn.f16x2.f32 %0, %1, %2;" : "=r"(r) : "f"(hi), "f"(lo));
    return r;
}

__device__ __forceinline__ uint32_t ex2h2(uint32_t a) {
    uint32_t d;
    asm("ex2.approx.f16x2 %0, %1;" : "=r"(d) : "r"(a));
    return d;
}

__device__ __forceinline__ void mma_f16(float c[4], const uint32_t a[4],
                                        uint32_t b0, uint32_t b1) {
    asm volatile(
        "mma.sync.aligned.m16n8k16.row.col.f32.f16.f16.f32 "
        "{%0,%1,%2,%3}, {%4,%5,%6,%7}, {%8,%9}, {%0,%1,%2,%3};\n"
        : "+f"(c[0]), "+f"(c[1]), "+f"(c[2]), "+f"(c[3])
        : "r"(a[0]), "r"(a[1]), "r"(a[2]), "r"(a[3]), "r"(b0), "r"(b1));
}

__device__ __forceinline__ void ldsm4(uint32_t r[4], uint32_t addr) {
    asm volatile("ldmatrix.sync.aligned.m8n8.x4.shared.b16 {%0,%1,%2,%3}, [%4];\n"
        : "=r"(r[0]), "=r"(r[1]), "=r"(r[2]), "=r"(r[3]) : "r"(addr));
}
__device__ __forceinline__ void ldsm4t(uint32_t r[4], uint32_t addr) {
    asm volatile("ldmatrix.sync.aligned.m8n8.x4.trans.shared.b16 {%0,%1,%2,%3}, [%4];\n"
        : "=r"(r[0]), "=r"(r[1]), "=r"(r[2]), "=r"(r[3]) : "r"(addr));
}

__device__ __forceinline__ void cpa16(uint32_t dst, const void* src) {
    asm volatile("cp.async.cg.shared.global [%0], [%1], 16;\n" :: "r"(dst), "l"(src));
}
#define CP_COMMIT() asm volatile("cp.async.commit_group;\n" ::: "memory")
#define CP_WAIT0()  asm volatile("cp.async.wait_group 0;\n" ::: "memory")
#define CP_WAIT1()  asm volatile("cp.async.wait_group 1;\n" ::: "memory")

// ---------------------------------------------------------------------------
// Merged converter: blocks [0,4096) convert X; [4096, 5632) convert W^T.
// ---------------------------------------------------------------------------
__global__ __launch_bounds__(256) void cvtAll(
    const float* __restrict__ X,
    const float* __restrict__ Wq, const float* __restrict__ Wk,
    const float* __restrict__ Wv)
{
    int bid = blockIdx.x;
    if (bid < 4096) {
        int idx = bid * 256 + threadIdx.x;
        float4 v = *reinterpret_cast<const float4*>(&X[(size_t)idx * 4]);
        uint2 u = {packh2(v.x, v.y), packh2(v.z, v.w)};
        *reinterpret_cast<uint2*>(&g_Xw[(size_t)idx * 2]) = u;
    } else {
        int id2 = bid - 4096;            // 0..1535
        int z   = id2 >> 9;              // 0..2
        const float* W = (z == 0) ? Wq : (z == 1) ? Wk : Wv;
        int id = (id2 & 511) * 256 + threadIdx.x;
        int pg = id >> 10;
        int n  = id & 1023;
        float w[8];
#pragma unroll
        for (int j = 0; j < 8; j++) w[j] = W[(size_t)(pg * 8 + j) * H_ + n];
        uint4 u = {packh2(w[0], w[1]), packh2(w[2], w[3]),
                   packh2(w[4], w[5]), packh2(w[6], w[7])};
        *reinterpret_cast<uint4*>(&g_Ww[(size_t)z * 524288 + (size_t)n * 512 + pg * 4]) = u;
    }
}

// ---------------------------------------------------------------------------
// Fused QKV GEMM (R14: 3-stage cp.async, single barrier/chunk, no reg cap).
// ---------------------------------------------------------------------------
__global__ __launch_bounds__(256) void qkv_gemm(
    const float* __restrict__ bq, const float* __restrict__ bk,
    const float* __restrict__ bv)
{
    extern __shared__ __align__(128) uint32_t smq[];

    const int z = blockIdx.z;
    const float* bias = (z == 0) ? bq : (z == 1) ? bk : bv;

    const int tid   = threadIdx.x;
    const int wid   = tid >> 5;
    const int lane  = tid & 31;
    const int g     = lane >> 2;
    const int tg    = lane & 3;
    const int warpM = wid >> 1;
    const int warpN = wid & 1;
    const int row0  = blockIdx.y * 128;
    const int col0  = blockIdx.x * 128;

    const uint32_t AO = (uint32_t)__cvta_generic_to_shared(smq);   // 3 x 10240 B
    const uint32_t BO = AO + 30720;                                 // 3 x 10240 B
    const uint32_t* Wz = g_Ww + (size_t)z * 524288;

    const int m8 = lane >> 3;
    const int r8 = lane & 7;
    const uint32_t abase = AO + (uint32_t)(((warpM * 32 + (m8 & 1) * 8 + r8) * 20 + (m8 >> 1) * 4) * 4);
    const uint32_t bbase = BO + (uint32_t)(((warpN * 64 + (m8 >> 1) * 8 + r8) * 20) * 4 + (m8 & 1) * 16);

    float c[2][8][4];
#pragma unroll
    for (int mt = 0; mt < 2; mt++)
#pragma unroll
        for (int nt = 0; nt < 8; nt++)
#pragma unroll
            for (int j = 0; j < 4; j++) c[mt][nt][j] = 0.f;

    auto stage = [&](int kc, int buf) {
#pragma unroll
        for (int p = 0; p < 2; p++) {
            int cid = p * 256 + tid;
            int r = cid >> 2, ch = cid & 3;
            cpa16(AO + (uint32_t)(buf * 10240 + r * 80 + ch * 16),
                  g_Xw + (size_t)(row0 + r) * 512 + kc * 16 + ch * 4);
            cpa16(BO + (uint32_t)(buf * 10240 + r * 80 + ch * 16),
                  Wz + (size_t)(col0 + r) * 512 + kc * 16 + ch * 4);
        }
    };

    stage(0, 0); CP_COMMIT();
    stage(1, 1); CP_COMMIT();

    int buf = 0;
    for (int kc = 0; kc < 32; kc++) {
        CP_WAIT1();
        __syncthreads();
        if (kc + 2 < 32) stage(kc + 2, (buf + 2) % 3);
        CP_COMMIT();
        const uint32_t ofs = (uint32_t)(buf * 10240);

#pragma unroll
        for (int kk = 0; kk < 2; kk++) {
            uint32_t a[2][4];
            ldsm4(a[0], abase + ofs + kk * 32);
            ldsm4(a[1], abase + ofs + 16 * 80 + kk * 32);
#pragma unroll
            for (int ntp = 0; ntp < 4; ntp++) {
                uint32_t bb[4];
                ldsm4(bb, bbase + ofs + ntp * 16 * 80 + kk * 32);
                mma_f16(c[0][2 * ntp],     a[0], bb[0], bb[1]);
                mma_f16(c[1][2 * ntp],     a[1], bb[0], bb[1]);
                mma_f16(c[0][2 * ntp + 1], a[0], bb[2], bb[3]);
                mma_f16(c[1][2 * ntp + 1], a[1], bb[2], bb[3]);
            }
        }
        buf = (buf + 1) % 3;
    }

    const int head = ((col0 + warpN * 64) >> 6);
#pragma unroll
    for (int mt = 0; mt < 2; mt++) {
#pragma unroll
        for (int nt = 0; nt < 8; nt++) {
            int dd   = nt * 8 + 2 * tg;
            int coln = col0 + warpN * 64 + dd;
            float b0 = bias[coln], b1 = bias[coln + 1];
            int r0 = row0 + warpM * 32 + mt * 16 + g;
            int r1 = r0 + 8;
            int bb0 = r0 >> 11, s0 = r0 & 2047;
            int bb1 = r1 >> 11, s1 = r1 & 2047;
            g_QKVw[z][((size_t)(bb0 * NH_ + head) * S_ + s0) * 32 + (dd >> 1)] =
                packh2(c[mt][nt][0] + b0, c[mt][nt][1] + b1);
            g_QKVw[z][((size_t)(bb1 * NH_ + head) * S_ + s1) * 32 + (dd >> 1)] =
                packh2(c[mt][nt][2] + b0, c[mt][nt][3] + b1);
        }
    }
}

// ---------------------------------------------------------------------------
// Flash attention, split-K (2 splits), FUSED combine: each split writes its
// unnormalized partial; the last-arriving block (per bh,qt; atomic counter)
// adds the peer's partial to its register copy, normalizes, writes out, and
// resets the flag for the next graph replay.
// ---------------------------------------------------------------------------
__global__ __launch_bounds__(128, 3) void attention(
    const float* __restrict__ mask, float* __restrict__ out)
{
    extern __shared__ __align__(128) uint32_t smu[];
    float* msk = (float*)(smu + 13824);       // [1024] pre-scaled by log2(e)

    const int tid  = threadIdx.x;
    const int w    = tid >> 5;
    const int lane = tid & 31;
    const int g    = lane >> 2;
    const int tg   = lane & 3;
    const int rb   = w * 32;
    const int qt    = blockIdx.x;
    const int head  = blockIdx.y;
    const int b     = blockIdx.z >> 1;
    const int split = blockIdx.z & 1;
    const int bh    = b * NH_ + head;

    const uint32_t smb = (uint32_t)__cvta_generic_to_shared(smu);
    const uint32_t QO = smb;                 // 18432 B
    const uint32_t KO = smb + 18432;         // 2 x 9216 B
    const uint32_t VO = smb + 36864;         // 2 x 9216 B ; msk @55296 (4 KB)

    const uint32_t* Qsrc = g_QKVw[0] + ((size_t)bh * S_ + qt * 128) * 32;
    const uint32_t* Ksrc = g_QKVw[1] + ((size_t)bh * S_ + split * 1024) * 32;
    const uint32_t* Vsrc = g_QKVw[2] + ((size_t)bh * S_ + split * 1024) * 32;

    const int m8 = lane >> 3;
    const int r8 = lane & 7;
    const uint32_t qbase = QO + (uint32_t)(((rb + (m8 & 1) * 8 + r8) * 36 + (m8 >> 1) * 4) * 4);
    const uint32_t kbase = (uint32_t)(((m8 >> 1) * 8 + r8) * 144 + (m8 & 1) * 16);
    const uint32_t vbase = (uint32_t)(((m8 & 1) * 8 + r8) * 144 + (m8 >> 1) * 16);

    auto stageKV = [&](int t, int buf) {
#pragma unroll
        for (int p = 0; p < 4; p++) {
            int cid = p * 128 + tid;
            int r = cid >> 3, ch = cid & 7;
            cpa16(KO + (uint32_t)(buf * 9216 + r * 144 + ch * 16),
                  Ksrc + (size_t)(t * 64 + r) * 32 + ch * 4);
            cpa16(VO + (uint32_t)(buf * 9216 + r * 144 + ch * 16),
                  Vsrc + (size_t)(t * 64 + r) * 32 + ch * 4);
        }
    };

#pragma unroll
    for (int p = 0; p < 8; p++) {
        int cid = p * 128 + tid;
        int r = cid >> 3, ch = cid & 7;
        cpa16(QO + (uint32_t)(r * 144 + ch * 16), Qsrc + (size_t)r * 32 + ch * 4);
    }
    stageKV(0, 0);
    CP_COMMIT();
    for (int i = tid; i < 1024; i += 128)
        msk[i] = mask[(size_t)b * S_ + split * 1024 + i] * LOG2E;

    float o[2][8][4];
#pragma unroll
    for (int mt = 0; mt < 2; mt++)
#pragma unroll
        for (int nt = 0; nt < 8; nt++)
#pragma unroll
            for (int j = 0; j < 4; j++) o[mt][nt][j] = 0.f;
    float lsum[2][4];
#pragma unroll
    for (int mt = 0; mt < 2; mt++)
#pragma unroll
        for (int j = 0; j < 4; j++) lsum[mt][j] = 0.f;

    const uint32_t ONES = 0x3C003C00u;

    for (int t = 0; t < 16; t++) {
        CP_WAIT0();
        __syncthreads();
        if (t + 1 < 16) stageKV(t + 1, (t + 1) & 1);
        CP_COMMIT();

        const uint32_t Kbuf = KO + (t & 1) * 9216 + kbase;
        const uint32_t Vbuf = VO + (t & 1) * 9216 + vbase;
        const float2* mrow = (const float2*)(msk + t * 64) + tg;

        float s[2][8][4];
#pragma unroll
        for (int mt = 0; mt < 2; mt++)
#pragma unroll
            for (int nt = 0; nt < 8; nt++)
#pragma unroll
                for (int j = 0; j < 4; j++) s[mt][nt][j] = 0.f;

#pragma unroll
        for (int kk = 0; kk < 4; kk++) {
            uint32_t aq[2][4];
            ldsm4(aq[0], qbase + kk * 32);
            ldsm4(aq[1], qbase + 2304 + kk * 32);
#pragma unroll
            for (int ntp = 0; ntp < 4; ntp++) {
                uint32_t kb[4];
                ldsm4(kb, Kbuf + ntp * 2304 + kk * 32);
                mma_f16(s[0][2 * ntp],     aq[0], kb[0], kb[1]);
                mma_f16(s[1][2 * ntp],     aq[1], kb[0], kb[1]);
                mma_f16(s[0][2 * ntp + 1], aq[0], kb[2], kb[3]);
                mma_f16(s[1][2 * ntp + 1], aq[1], kb[2], kb[3]);
            }
        }

        uint32_t ps[2][8][2];
#pragma unroll
        for (int mt = 0; mt < 2; mt++) {
#pragma unroll
            for (int nt = 0; nt < 8; nt++) {
                float2 mv = mrow[nt * 4];
                float a0 = fminf(s[mt][nt][0] * SCL + mv.x, 15.f);
                float a1 = fminf(s[mt][nt][1] * SCL + mv.y, 15.f);
                float a2 = fminf(s[mt][nt][2] * SCL + mv.x, 15.f);
                float a3 = fminf(s[mt][nt][3] * SCL + mv.y, 15.f);
                ps[mt][nt][0] = ex2h2(packh2(a0, a1));
                ps[mt][nt][1] = ex2h2(packh2(a2, a3));
            }
        }

#pragma unroll
        for (int kk = 0; kk < 4; kk++) {
            uint32_t ap[2][4];
#pragma unroll
            for (int mt = 0; mt < 2; mt++) {
                ap[mt][0] = ps[mt][2 * kk][0];
                ap[mt][1] = ps[mt][2 * kk][1];
                ap[mt][2] = ps[mt][2 * kk + 1][0];
                ap[mt][3] = ps[mt][2 * kk + 1][1];
            }
            mma_f16(lsum[0], ap[0], ONES, ONES);
            mma_f16(lsum[1], ap[1], ONES, ONES);
#pragma unroll
            for (int ntp = 0; ntp < 4; ntp++) {
                uint32_t vb[4];
                ldsm4t(vb, Vbuf + kk * 2304 + ntp * 32);
                mma_f16(o[0][2 * ntp],     ap[0], vb[0], vb[1]);
                mma_f16(o[1][2 * ntp],     ap[1], vb[0], vb[1]);
                mma_f16(o[0][2 * ntp + 1], ap[0], vb[2], vb[3]);
                mma_f16(o[1][2 * ntp + 1], ap[1], vb[2], vb[3]);
            }
        }
    }

    // ---- Epilogue: publish partial, then last-arriving block combines.
    {
        float* Op = g_Op[split] + (size_t)bh * S_ * D_;
        float* Lp = g_L[split] + (size_t)bh * S_;
#pragma unroll
        for (int mt = 0; mt < 2; mt++) {
            int r0 = qt * 128 + rb + mt * 16 + g;
            int r1 = r0 + 8;
#pragma unroll
            for (int nt = 0; nt < 8; nt++) {
                int dd = nt * 8 + 2 * tg;
                float2 v0 = {o[mt][nt][0], o[mt][nt][1]};
                float2 v1 = {o[mt][nt][2], o[mt][nt][3]};
                *reinterpret_cast<float2*>(&Op[(size_t)r0 * D_ + dd]) = v0;
                *reinterpret_cast<float2*>(&Op[(size_t)r1 * D_ + dd]) = v1;
            }
            if (tg == 0) {
                Lp[r0] = lsum[mt][0];
                Lp[r1] = lsum[mt][2];
            }
        }
        __threadfence();

        int* flag = &g_flag[bh * 16 + qt];
        if (tid == 0) smu[0] = (uint32_t)(atomicAdd(flag, 1) == 1);
        __syncthreads();
        if (smu[0]) {
            __threadfence();   // acquire: peer's partial now visible
            const float* Oq = g_Op[1 - split] + (size_t)bh * S_ * D_;
            const float* Lq = g_L[1 - split] + (size_t)bh * S_;
#pragma unroll
            for (int mt = 0; mt < 2; mt++) {
                int r0 = qt * 128 + rb + mt * 16 + g;
                int r1 = r0 + 8;
                float i0 = 1.0f / (lsum[mt][0] + Lq[r0]);
                float i1 = 1.0f / (lsum[mt][2] + Lq[r1]);
#pragma unroll
                for (int nt = 0; nt < 8; nt++) {
                    int dd = nt * 8 + 2 * tg;
                    float2 p0 = *reinterpret_cast<const float2*>(&Oq[(size_t)r0 * D_ + dd]);
                    float2 p1 = *reinterpret_cast<const float2*>(&Oq[(size_t)r1 * D_ + dd]);
                    float2 v0 = {(o[mt][nt][0] + p0.x) * i0, (o[mt][nt][1] + p0.y) * i0};
                    float2 v1 = {(o[mt][nt][2] + p1.x) * i1, (o[mt][nt][3] + p1.y) * i1};
                    int gd = head * 64 + dd;
                    *reinterpret_cast<float2*>(&out[((size_t)b * S_ + r0) * H_ + gd]) = v0;
                    *reinterpret_cast<float2*>(&out[((size_t)b * S_ + r1) * H_ + gd]) = v1;
                }
            }
            if (tid == 0) *flag = 0;   // reset for next graph replay
        }
    }
}

// ---------------------------------------------------------------------------
extern "C" void kernel_launch(void* const* d_in, const int* in_sizes, int n_in,
                              void* d_out, int out_size)
{
    const float* hs   = (const float*)d_in[0];
    const float* mask = (const float*)d_in[1];
    const float* Wq   = (const float*)d_in[2];
    const float* bq   = (const float*)d_in[3];
    const float* Wk   = (const float*)d_in[4];
    const float* bk   = (const float*)d_in[5];
    const float* Wv   = (const float*)d_in[6];
    const float* bv   = (const float*)d_in[7];
    float* out = (float*)d_out;

    cudaFuncSetAttribute(qkv_gemm, cudaFuncAttributeMaxDynamicSharedMemorySize, 61440);
    cudaFuncSetAttribute(attention, cudaFuncAttributeMaxDynamicSharedMemorySize, 59392);

    cvtAll<<<5632, 256>>>(hs, Wq, Wk, Wv);

    dim3 ggemm(H_ / 128, (B_ * S_) / 128, 3);   // fused Q/K/V
    qkv_gemm<<<ggemm, 256, 61440>>>(bq, bk, bv);

    dim3 gattn(S_ / 128, NH_, B_ * 2);          // (16, 16, 4) — 2 KV splits
    attention<<<gattn, 128, 59392>>>(mask, out);
}